// round 7
// baseline (speedup 1.0000x reference)
#include <cuda_runtime.h>
#include <cuda_bf16.h>
#include <stdint.h>

#define N_NODES    100000
#define N_EDGES    1600000
#define HID        128
#define OUT_CH     10
#define NUM_GRAPHS 512

// ---------------- scratch (static device globals; kernel launches are the
// ONLY host API used in kernel_launch) ---------------------------------------
__device__ float g_h0[N_NODES * HID];
__device__ float g_h1[N_NODES * HID];
__device__ int   g_rowptr[N_NODES + 1];
__device__ int   g_cnt[N_NODES];
__device__ int   g_local[N_NODES];
__device__ int   g_bsums[128];
__device__ int   g_col[N_EDGES];
__device__ int   g_start[NUM_GRAPHS + 1];

__device__ __forceinline__ const float* sel_buf(int sel, const float* ext) {
    if (sel == 0) return g_h0;
    if (sel == 1) return g_h1;
    return ext;
}

__device__ __forceinline__ void split_bf16(float x, __nv_bfloat16& h, __nv_bfloat16& l) {
    h = __float2bfloat16(x);
    l = __float2bfloat16(x - __bfloat162float(h));
}
__device__ __forceinline__ uint32_t pack2(__nv_bfloat16 lo, __nv_bfloat16 hi) {
    return (uint32_t)__bfloat16_as_ushort(lo) | ((uint32_t)__bfloat16_as_ushort(hi) << 16);
}
__device__ __forceinline__ void mma_bf16(float c[4], uint32_t a0, uint32_t a1,
                                         uint32_t a2, uint32_t a3,
                                         uint32_t b0, uint32_t b1) {
    asm volatile(
        "mma.sync.aligned.m16n8k16.row.col.f32.bf16.bf16.f32 "
        "{%0,%1,%2,%3}, {%4,%5,%6,%7}, {%8,%9}, {%0,%1,%2,%3};\n"
        : "+f"(c[0]), "+f"(c[1]), "+f"(c[2]), "+f"(c[3])
        : "r"(a0), "r"(a1), "r"(a2), "r"(a3), "r"(b0), "r"(b1));
}

// ---------------- zero counters --------------------------------------------
__global__ void zero_cnt_kernel() {
    int i = blockIdx.x * blockDim.x + threadIdx.x;
    if (i < N_NODES) g_cnt[i] = 0;
}

// ---------------- CSR build (edge_index is int32) ---------------------------
__global__ void hist_kernel(const int* __restrict__ ei) {
    int e = blockIdx.x * blockDim.x + threadIdx.x;
    if (e >= N_EDGES) return;
    atomicAdd(&g_cnt[ei[N_EDGES + e]], 1);
}

__global__ void scan_local_kernel() {
    __shared__ int s[1024];
    int tid = threadIdx.x;
    int i = blockIdx.x * 1024 + tid;
    int v = (i < N_NODES) ? g_cnt[i] : 0;
    s[tid] = v;
    __syncthreads();
    for (int off = 1; off < 1024; off <<= 1) {
        int t = (tid >= off) ? s[tid - off] : 0;
        __syncthreads();
        s[tid] += t;
        __syncthreads();
    }
    if (i < N_NODES) g_local[i] = s[tid] - v;
    if (tid == 1023) g_bsums[blockIdx.x] = s[1023];
}

__global__ void scan_sums_kernel(int nb) {
    if (threadIdx.x == 0 && blockIdx.x == 0) {
        int run = 0;
        for (int i = 0; i < nb; i++) { int v = g_bsums[i]; g_bsums[i] = run; run += v; }
    }
}

__global__ void scan_add_kernel() {
    int i = blockIdx.x * blockDim.x + threadIdx.x;
    if (i < N_NODES) g_rowptr[i] = g_local[i] + g_bsums[i >> 10];
    if (i == 0) g_rowptr[N_NODES] = N_EDGES;
}

__global__ void fill_kernel(const int* __restrict__ ei) {
    int e = blockIdx.x * blockDim.x + threadIdx.x;
    if (e >= N_EDGES) return;
    int d = ei[N_EDGES + e];
    int s = ei[e];
    int pos = g_rowptr[d] + atomicAdd(&g_cnt[d], 1);
    g_col[pos] = s;
}

// ============ fused GIN layer: gather + HMMA MLP ============================
// Block: 64 nodes x 128 out-ch, 256 threads = 8 warps (2m x 4n), warp 32x32.
// Phase 1: each warp gathers 8 node rows (h[self]+sum h[nbr], fp32) and
// writes the hi/lo-split A tile to smem. Phase 2: two mma.sync GEMM stages.
// SMEM (words): A_hi[64][68], A_lo[64][68], W panel hi/lo [128][9], biases.
#define A_ST  68
#define WB_ST 9
#define A_HI  0
#define A_LO  4352
#define WB_HI 8704
#define WB_LO 9856
#define BS1   11008
#define BS2   11136
#define SM_WORDS 11264

__device__ __forceinline__ void mma_stage(uint32_t* sm, const float* __restrict__ W,
                                          int tid, int gid, int tig, int m0, int n0,
                                          float acc[2][4][4]) {
#pragma unroll 1
    for (int p = 0; p < 8; p++) {
        // prefetch panel p to regs: 4 items of (n, kp_local)
        float w0[4], w1[4];
#pragma unroll
        for (int it = 0; it < 4; it++) {
            int i = it * 256 + tid;
            int n = i & 127, kpl = i >> 7;
            int kg = p * 16 + kpl * 2;
            w0[it] = W[kg * HID + n];
            w1[it] = W[(kg + 1) * HID + n];
        }
        __syncthreads();   // previous panel fully consumed (also orders A writes)
#pragma unroll
        for (int it = 0; it < 4; it++) {
            int i = it * 256 + tid;
            int n = i & 127, kpl = i >> 7;
            __nv_bfloat16 h0, l0, h1, l1;
            split_bf16(w0[it], h0, l0);
            split_bf16(w1[it], h1, l1);
            sm[WB_HI + n * WB_ST + kpl] = pack2(h0, h1);
            sm[WB_LO + n * WB_ST + kpl] = pack2(l0, l1);
        }
        __syncthreads();   // panel visible

        // A fragments for this k-step (kpairs p*8 .. p*8+7)
        uint32_t ah[2][4], al[2][4];
#pragma unroll
        for (int mt = 0; mt < 2; mt++) {
            int base = (m0 + mt * 16 + gid) * A_ST + p * 8;
            ah[mt][0] = sm[A_HI + base + tig];
            ah[mt][1] = sm[A_HI + base + 8 * A_ST + tig];
            ah[mt][2] = sm[A_HI + base + 4 + tig];
            ah[mt][3] = sm[A_HI + base + 8 * A_ST + 4 + tig];
            al[mt][0] = sm[A_LO + base + tig];
            al[mt][1] = sm[A_LO + base + 8 * A_ST + tig];
            al[mt][2] = sm[A_LO + base + 4 + tig];
            al[mt][3] = sm[A_LO + base + 8 * A_ST + 4 + tig];
        }
#pragma unroll
        for (int nt = 0; nt < 4; nt++) {
            int nb = (n0 + nt * 8 + gid) * WB_ST;
            uint32_t b0h = sm[WB_HI + nb + tig];
            uint32_t b1h = sm[WB_HI + nb + 4 + tig];
            uint32_t b0l = sm[WB_LO + nb + tig];
            uint32_t b1l = sm[WB_LO + nb + 4 + tig];
#pragma unroll
            for (int mt = 0; mt < 2; mt++) {
                mma_bf16(acc[mt][nt], ah[mt][0], ah[mt][1], ah[mt][2], ah[mt][3], b0h, b1h);
                mma_bf16(acc[mt][nt], ah[mt][0], ah[mt][1], ah[mt][2], ah[mt][3], b0l, b1l);
                mma_bf16(acc[mt][nt], al[mt][0], al[mt][1], al[mt][2], al[mt][3], b0h, b1h);
            }
        }
    }
}

__global__ __launch_bounds__(256, 2) void gin_layer_kernel(const float* __restrict__ x_ext,
                                                           int in_sel,
                                                           const float* __restrict__ W1,
                                                           const float* __restrict__ B1,
                                                           const float* __restrict__ W2,
                                                           const float* __restrict__ B2,
                                                           int out_sel, int reluOut) {
    __shared__ uint32_t sm[SM_WORDS];
    const float* __restrict__ h = sel_buf(in_sel, x_ext);
    float* O = (out_sel == 0) ? g_h0 : g_h1;
    float* bs1 = (float*)(sm + BS1);
    float* bs2 = (float*)(sm + BS2);

    int tid  = threadIdx.x;
    int lane = tid & 31, warp = tid >> 5;
    int gid  = lane >> 2, tig = lane & 3;
    int m0   = (warp & 1) * 32;
    int n0   = (warp >> 1) * 32;
    int row0 = blockIdx.x * 64;

    if (tid < 128) { bs1[tid] = B1[tid]; bs2[tid] = B2[tid]; }

    // ---- phase 1: gather z = h[self] + sum h[nbr], split into A tile ----
    {
        int co = lane * 4;            // channel for this lane
        int kp = lane * 2;            // kpair word index
#pragma unroll 1
        for (int i = 0; i < 8; i++) {
            int r = warp * 8 + i;     // tile row 0..63
            int node = row0 + r;
            float4 acc = make_float4(0.f, 0.f, 0.f, 0.f);
            if (node < N_NODES) {
                acc = *(const float4*)(h + (size_t)node * HID + co);
                int e = g_rowptr[node];
                int end = g_rowptr[node + 1];
                for (; e + 4 <= end; e += 4) {
                    int s0 = g_col[e], s1 = g_col[e + 1];
                    int s2 = g_col[e + 2], s3 = g_col[e + 3];
                    float4 v0 = *(const float4*)(h + (size_t)s0 * HID + co);
                    float4 v1 = *(const float4*)(h + (size_t)s1 * HID + co);
                    float4 v2 = *(const float4*)(h + (size_t)s2 * HID + co);
                    float4 v3 = *(const float4*)(h + (size_t)s3 * HID + co);
                    acc.x += v0.x + v1.x + v2.x + v3.x;
                    acc.y += v0.y + v1.y + v2.y + v3.y;
                    acc.z += v0.z + v1.z + v2.z + v3.z;
                    acc.w += v0.w + v1.w + v2.w + v3.w;
                }
                for (; e < end; e++) {
                    int s = g_col[e];
                    float4 v = *(const float4*)(h + (size_t)s * HID + co);
                    acc.x += v.x; acc.y += v.y; acc.z += v.z; acc.w += v.w;
                }
            }
            __nv_bfloat16 hx, lx, hy, ly, hz, lz, hw, lw;
            split_bf16(acc.x, hx, lx); split_bf16(acc.y, hy, ly);
            split_bf16(acc.z, hz, lz); split_bf16(acc.w, hw, lw);
            sm[A_HI + r * A_ST + kp]     = pack2(hx, hy);
            sm[A_HI + r * A_ST + kp + 1] = pack2(hz, hw);
            sm[A_LO + r * A_ST + kp]     = pack2(lx, ly);
            sm[A_LO + r * A_ST + kp + 1] = pack2(lz, lw);
        }
    }
    // ordering: A writes precede the A-frag reads via mma_stage's barriers

    float acc[2][4][4];
#pragma unroll
    for (int mt = 0; mt < 2; mt++)
#pragma unroll
        for (int nt = 0; nt < 4; nt++)
#pragma unroll
            for (int q = 0; q < 4; q++) acc[mt][nt][q] = 0.f;

    // ---- stage 1 ----
    mma_stage(sm, W1, tid, gid, tig, m0, n0, acc);

    // ---- epilogue 1: bias+relu, write H1 over A (all stage-1 reads done) ----
    __syncthreads();
#pragma unroll
    for (int mt = 0; mt < 2; mt++) {
#pragma unroll
        for (int nt = 0; nt < 4; nt++) {
            int col = n0 + nt * 8 + 2 * tig;
            float bia0 = bs1[col], bia1 = bs1[col + 1];
            int kp2 = ((n0 + nt * 8) >> 1) + tig;
            int ra = m0 + mt * 16 + gid;
            float v0 = fmaxf(acc[mt][nt][0] + bia0, 0.f);
            float v1 = fmaxf(acc[mt][nt][1] + bia1, 0.f);
            float v2 = fmaxf(acc[mt][nt][2] + bia0, 0.f);
            float v3 = fmaxf(acc[mt][nt][3] + bia1, 0.f);
            __nv_bfloat16 h0, l0, h1, l1, h2, l2, h3, l3;
            split_bf16(v0, h0, l0); split_bf16(v1, h1, l1);
            split_bf16(v2, h2, l2); split_bf16(v3, h3, l3);
            sm[A_HI + ra * A_ST + kp2]       = pack2(h0, h1);
            sm[A_LO + ra * A_ST + kp2]       = pack2(l0, l1);
            sm[A_HI + (ra + 8) * A_ST + kp2] = pack2(h2, h3);
            sm[A_LO + (ra + 8) * A_ST + kp2] = pack2(l2, l3);
#pragma unroll
            for (int q = 0; q < 4; q++) acc[mt][nt][q] = 0.f;
        }
    }
    // stage 2's first __syncthreads orders these writes before panel store;
    // A-frag reads happen after the second barrier.

    // ---- stage 2 ----
    mma_stage(sm, W2, tid, gid, tig, m0, n0, acc);

    // ---- epilogue 2: bias (+relu), float2 STG ----
#pragma unroll
    for (int mt = 0; mt < 2; mt++) {
#pragma unroll
        for (int nt = 0; nt < 4; nt++) {
            int col = n0 + nt * 8 + 2 * tig;
            float bia0 = bs2[col], bia1 = bs2[col + 1];
            int node0 = row0 + m0 + mt * 16 + gid;
            float2 o0, o1;
            o0.x = acc[mt][nt][0] + bia0; o0.y = acc[mt][nt][1] + bia1;
            o1.x = acc[mt][nt][2] + bia0; o1.y = acc[mt][nt][3] + bia1;
            if (reluOut) {
                o0.x = fmaxf(o0.x, 0.f); o0.y = fmaxf(o0.y, 0.f);
                o1.x = fmaxf(o1.x, 0.f); o1.y = fmaxf(o1.y, 0.f);
            }
            if (node0 < N_NODES)
                *(float2*)(O + (size_t)node0 * HID + col) = o0;
            if (node0 + 8 < N_NODES)
                *(float2*)(O + (size_t)(node0 + 8) * HID + col) = o1;
        }
    }
}

// ---------------- pooling boundaries (batch is sorted int32) ---------------
__global__ void boundaries_kernel(const int* __restrict__ batch) {
    int i = blockIdx.x * blockDim.x + threadIdx.x;
    if (i >= N_NODES) return;
    int b = batch[i];
    if (i == 0) {
        for (int g = 0; g <= b; g++) g_start[g] = 0;
    } else {
        int p = batch[i - 1];
        if (p < b)
            for (int g = p + 1; g <= b; g++) g_start[g] = i;
    }
    if (i == N_NODES - 1) {
        for (int g = b + 1; g <= NUM_GRAPHS; g++) g_start[g] = N_NODES;
    }
}

// ---------------- fused global_add_pool + final linear ---------------------
__global__ void pool_final_kernel(const float* __restrict__ lw,
                                  const float* __restrict__ lb,
                                  float* __restrict__ out,
                                  int in_sel) {
    const float* __restrict__ h = (in_sel == 0) ? g_h0 : g_h1;
    int g = blockIdx.x;
    int c = threadIdx.x;   // 128 threads
    int s = g_start[g], e = g_start[g + 1];
    float acc = 0.f;
    for (int n = s; n < e; n++) acc += h[(size_t)n * HID + c];
    __shared__ float sp[HID];
    sp[c] = acc;
    __syncthreads();
    if (c < OUT_CH) {
        float o = lb[c];
#pragma unroll 8
        for (int k = 0; k < HID; k++) o += sp[k] * lw[k * OUT_CH + c];
        out[g * OUT_CH + c] = o;
    }
}

// ---------------- host: kernel launches ONLY -------------------------------
extern "C" void kernel_launch(void* const* d_in, const int* in_sizes, int n_in,
                              void* d_out, int out_size) {
    const float* x     = (const float*)d_in[0];
    const int*   ei    = (const int*)d_in[1];     // int32 (JAX x64 disabled)
    const int*   batch = (const int*)d_in[2];     // int32
    const float* w1[3] = {(const float*)d_in[3],  (const float*)d_in[7],  (const float*)d_in[11]};
    const float* b1[3] = {(const float*)d_in[4],  (const float*)d_in[8],  (const float*)d_in[12]};
    const float* w2[3] = {(const float*)d_in[5],  (const float*)d_in[9],  (const float*)d_in[13]};
    const float* b2[3] = {(const float*)d_in[6],  (const float*)d_in[10], (const float*)d_in[14]};
    const float* lin_w = (const float*)d_in[15];
    const float* lin_b = (const float*)d_in[16];
    float* out = (float*)d_out;

    // ---- CSR build (deterministic per launch) ----
    zero_cnt_kernel<<<(N_NODES + 255) / 256, 256>>>();
    hist_kernel<<<(N_EDGES + 255) / 256, 256>>>(ei);
    scan_local_kernel<<<(N_NODES + 1023) / 1024, 1024>>>();
    scan_sums_kernel<<<1, 32>>>((N_NODES + 1023) / 1024);
    scan_add_kernel<<<(N_NODES + 255) / 256, 256>>>();
    zero_cnt_kernel<<<(N_NODES + 255) / 256, 256>>>();
    fill_kernel<<<(N_EDGES + 255) / 256, 256>>>(ei);
    boundaries_kernel<<<(N_NODES + 255) / 256, 256>>>(batch);

    // ---- 3 fused GIN layers (gather + MLP in one kernel) ----
    const int blocks = (N_NODES + 63) / 64;
    gin_layer_kernel<<<blocks, 256>>>(x, -1, w1[0], b1[0], w2[0], b2[0], 0, 1);
    gin_layer_kernel<<<blocks, 256>>>(nullptr, 0, w1[1], b1[1], w2[1], b2[1], 1, 1);
    gin_layer_kernel<<<blocks, 256>>>(nullptr, 1, w1[2], b1[2], w2[2], b2[2], 0, 0);

    // ---- pool + final linear ----
    pool_final_kernel<<<NUM_GRAPHS, 128>>>(lin_w, lin_b, out, 0);
}

// round 8
// speedup vs baseline: 1.1693x; 1.1693x over previous
#include <cuda_runtime.h>
#include <cuda_bf16.h>
#include <stdint.h>

#define N_NODES    100000
#define N_EDGES    1600000
#define HID        128
#define OUT_CH     10
#define NUM_GRAPHS 512

// ---------------- scratch (static device globals; kernel launches are the
// ONLY host API used in kernel_launch) ---------------------------------------
__device__ float g_h0[N_NODES * HID];
__device__ float g_h1[N_NODES * HID];
__device__ float g_z [N_NODES * HID];
__device__ int   g_rowptr[N_NODES + 1];
__device__ int   g_cnt[N_NODES];
__device__ int   g_local[N_NODES];
__device__ int   g_bsums[128];
__device__ int   g_col[N_EDGES];
__device__ int   g_start[NUM_GRAPHS + 1];

__device__ __forceinline__ const float* sel_buf(int sel, const float* ext) {
    if (sel == 0) return g_h0;
    if (sel == 1) return g_h1;
    return ext;
}

__device__ __forceinline__ void split_bf16(float x, __nv_bfloat16& h, __nv_bfloat16& l) {
    h = __float2bfloat16(x);
    l = __float2bfloat16(x - __bfloat162float(h));
}
__device__ __forceinline__ uint32_t pack2(__nv_bfloat16 lo, __nv_bfloat16 hi) {
    return (uint32_t)__bfloat16_as_ushort(lo) | ((uint32_t)__bfloat16_as_ushort(hi) << 16);
}
__device__ __forceinline__ void mma_bf16(float c[4], uint32_t a0, uint32_t a1,
                                         uint32_t a2, uint32_t a3,
                                         uint32_t b0, uint32_t b1) {
    asm volatile(
        "mma.sync.aligned.m16n8k16.row.col.f32.bf16.bf16.f32 "
        "{%0,%1,%2,%3}, {%4,%5,%6,%7}, {%8,%9}, {%0,%1,%2,%3};\n"
        : "+f"(c[0]), "+f"(c[1]), "+f"(c[2]), "+f"(c[3])
        : "r"(a0), "r"(a1), "r"(a2), "r"(a3), "r"(b0), "r"(b1));
}

// ---------------- zero counters --------------------------------------------
__global__ void zero_cnt_kernel() {
    int i = blockIdx.x * blockDim.x + threadIdx.x;
    if (i < N_NODES) g_cnt[i] = 0;
}

// ---------------- CSR build (edge_index is int32) ---------------------------
__global__ void hist_kernel(const int* __restrict__ ei) {
    int e = blockIdx.x * blockDim.x + threadIdx.x;
    if (e >= N_EDGES) return;
    atomicAdd(&g_cnt[ei[N_EDGES + e]], 1);
}

__global__ void scan_local_kernel() {
    __shared__ int s[1024];
    int tid = threadIdx.x;
    int i = blockIdx.x * 1024 + tid;
    int v = (i < N_NODES) ? g_cnt[i] : 0;
    s[tid] = v;
    __syncthreads();
    for (int off = 1; off < 1024; off <<= 1) {
        int t = (tid >= off) ? s[tid - off] : 0;
        __syncthreads();
        s[tid] += t;
        __syncthreads();
    }
    if (i < N_NODES) g_local[i] = s[tid] - v;
    if (tid == 1023) g_bsums[blockIdx.x] = s[1023];
}

__global__ void scan_sums_kernel(int nb) {
    if (threadIdx.x == 0 && blockIdx.x == 0) {
        int run = 0;
        for (int i = 0; i < nb; i++) { int v = g_bsums[i]; g_bsums[i] = run; run += v; }
    }
}

__global__ void scan_add_kernel() {
    int i = blockIdx.x * blockDim.x + threadIdx.x;
    if (i < N_NODES) g_rowptr[i] = g_local[i] + g_bsums[i >> 10];
    if (i == 0) g_rowptr[N_NODES] = N_EDGES;
}

__global__ void fill_kernel(const int* __restrict__ ei) {
    int e = blockIdx.x * blockDim.x + threadIdx.x;
    if (e >= N_EDGES) return;
    int d = ei[N_EDGES + e];
    int s = ei[e];
    int pos = g_rowptr[d] + atomicAdd(&g_cnt[d], 1);
    g_col[pos] = s;
}

// ---------------- aggregation: g_z = h + sum_{j in N(i)} h[j] --------------
__global__ __launch_bounds__(256) void aggregate_kernel(const float* __restrict__ x_ext,
                                                        int in_sel) {
    const float* __restrict__ h = sel_buf(in_sel, x_ext);
    int node = (blockIdx.x * blockDim.x + threadIdx.x) >> 5;
    int lane = threadIdx.x & 31;
    if (node >= N_NODES) return;
    int beg = g_rowptr[node];
    int end = g_rowptr[node + 1];
    int co = lane * 4;
    float4 acc = *(const float4*)(h + (size_t)node * HID + co);
    int e = beg;
    for (; e + 4 <= end; e += 4) {
        int s0 = g_col[e], s1 = g_col[e + 1], s2 = g_col[e + 2], s3 = g_col[e + 3];
        float4 v0 = *(const float4*)(h + (size_t)s0 * HID + co);
        float4 v1 = *(const float4*)(h + (size_t)s1 * HID + co);
        float4 v2 = *(const float4*)(h + (size_t)s2 * HID + co);
        float4 v3 = *(const float4*)(h + (size_t)s3 * HID + co);
        acc.x += v0.x + v1.x + v2.x + v3.x;
        acc.y += v0.y + v1.y + v2.y + v3.y;
        acc.z += v0.z + v1.z + v2.z + v3.z;
        acc.w += v0.w + v1.w + v2.w + v3.w;
    }
    for (; e < end; e++) {
        int s = g_col[e];
        float4 v = *(const float4*)(h + (size_t)s * HID + co);
        acc.x += v.x; acc.y += v.y; acc.z += v.z; acc.w += v.w;
    }
    *(float4*)(g_z + (size_t)node * HID + co) = acc;
}

// ============ HMMA MLP: bf16 hi/lo 3-term, fragment-major smem layouts ======
// Block: 64 nodes x 128 out-ch, 256 threads = 8 warps (2m x 4n), warp 32x32.
// A layout: per (16-row mtile, 8-kpair kgroup) 132-word tile; word (r,kp) at
//   lane'=(r&7)*4+(kp&3), w=((r>>3)&1)+2*((kp>>2)&1)  -> frag = 1 LDS.128.
// B panel layout: per 8-col ntile 66-word tile; word (n,kp) at
//   lane'=(n&7)*4+(kp&3), w=(kp>>2)&1                 -> frag = 1 LDS.64.
#define A_HI  0
#define A_LO  4224
#define WB_HI 8448
#define WB_LO 9504
#define BS1   10560
#define BS2   10688
#define SM_WORDS 10816

__device__ __forceinline__ int a_addr(int r, int kp) {
    return (((r >> 4) * 8) + (kp >> 3)) * 132
         + ((r & 7) * 4 + (kp & 3)) * 4
         + ((r >> 3) & 1) + 2 * ((kp >> 2) & 1);
}
__device__ __forceinline__ int b_addr(int n, int kp) {
    return (n >> 3) * 66 + ((n & 7) * 4 + (kp & 3)) * 2 + ((kp >> 2) & 1);
}

__device__ __forceinline__ void mma_stage(uint32_t* sm, const float* __restrict__ W,
                                          int tid, int lane, int m0, int n0,
                                          float acc[2][4][4]) {
    int m016 = m0 >> 4;        // 0 or 2
    int n08  = n0 >> 3;        // 0 or 4
#pragma unroll 1
    for (int p = 0; p < 8; p++) {
        // prefetch W panel p (k=16) to regs
        float w0[4], w1[4];
#pragma unroll
        for (int it = 0; it < 4; it++) {
            int i = it * 256 + tid;
            int n = i & 127, kpl = i >> 7;
            int kg = p * 16 + kpl * 2;
            w0[it] = W[kg * HID + n];
            w1[it] = W[(kg + 1) * HID + n];
        }
        __syncthreads();   // previous panel consumed (also orders A writes, p=0)
#pragma unroll
        for (int it = 0; it < 4; it++) {
            int i = it * 256 + tid;
            int n = i & 127, kpl = i >> 7;
            __nv_bfloat16 h0, l0, h1, l1;
            split_bf16(w0[it], h0, l0);
            split_bf16(w1[it], h1, l1);
            int ba = b_addr(n, kpl);
            sm[WB_HI + ba] = pack2(h0, h1);
            sm[WB_LO + ba] = pack2(l0, l1);
        }
        __syncthreads();   // panel visible

        // A fragments: one LDS.128 per (mtile, hi/lo)
        uint4 ah[2], al[2];
#pragma unroll
        for (int mt = 0; mt < 2; mt++) {
            int base = ((m016 + mt) * 8 + p) * 132 + lane * 4;
            ah[mt] = *(const uint4*)&sm[A_HI + base];
            al[mt] = *(const uint4*)&sm[A_LO + base];
        }
#pragma unroll
        for (int nt = 0; nt < 4; nt++) {
            int nb = (n08 + nt) * 66 + lane * 2;
            uint2 bh = *(const uint2*)&sm[WB_HI + nb];
            uint2 bl = *(const uint2*)&sm[WB_LO + nb];
#pragma unroll
            for (int mt = 0; mt < 2; mt++) {
                mma_bf16(acc[mt][nt], ah[mt].x, ah[mt].y, ah[mt].z, ah[mt].w, bh.x, bh.y);
                mma_bf16(acc[mt][nt], ah[mt].x, ah[mt].y, ah[mt].z, ah[mt].w, bl.x, bl.y);
                mma_bf16(acc[mt][nt], al[mt].x, al[mt].y, al[mt].z, al[mt].w, bh.x, bh.y);
            }
        }
    }
}

__global__ __launch_bounds__(256, 2) void mlp_mma_kernel(const float* __restrict__ W1,
                                                         const float* __restrict__ B1,
                                                         const float* __restrict__ W2,
                                                         const float* __restrict__ B2,
                                                         int out_sel, int reluOut) {
    __shared__ __align__(16) uint32_t sm[SM_WORDS];
    float* O = (out_sel == 0) ? g_h0 : g_h1;
    float* bs1 = (float*)(sm + BS1);
    float* bs2 = (float*)(sm + BS2);

    int tid  = threadIdx.x;
    int lane = tid & 31, warp = tid >> 5;
    int gid  = lane >> 2, tig = lane & 3;
    int m0   = (warp & 1) * 32;
    int n0   = (warp >> 1) * 32;
    int row0 = blockIdx.x * 64;

    if (tid < 128) { bs1[tid] = B1[tid]; bs2[tid] = B2[tid]; }

    // ---- load Z tile, hi/lo split, fragment-major A layout ----
#pragma unroll
    for (int p = 0; p < 8; p++) {
        int idx = p * 256 + tid;          // 0..2047
        int r  = idx >> 5;                // node row 0..63
        int c4 = (idx & 31) << 2;         // channel 0..124
        float4 v = make_float4(0.f, 0.f, 0.f, 0.f);
        if (row0 + r < N_NODES)
            v = *(const float4*)(g_z + (size_t)(row0 + r) * HID + c4);
        int kp = c4 >> 1;
        __nv_bfloat16 hx, lx, hy, ly, hz, lz, hw, lw;
        split_bf16(v.x, hx, lx); split_bf16(v.y, hy, ly);
        split_bf16(v.z, hz, lz); split_bf16(v.w, hw, lw);
        int a0i = a_addr(r, kp);
        int a1i = a_addr(r, kp + 1);
        sm[A_HI + a0i] = pack2(hx, hy);
        sm[A_HI + a1i] = pack2(hz, hw);
        sm[A_LO + a0i] = pack2(lx, ly);
        sm[A_LO + a1i] = pack2(lz, lw);
    }
    // ordering: A writes precede A-frag reads via mma_stage's barriers

    float acc[2][4][4];
#pragma unroll
    for (int mt = 0; mt < 2; mt++)
#pragma unroll
        for (int nt = 0; nt < 4; nt++)
#pragma unroll
            for (int q = 0; q < 4; q++) acc[mt][nt][q] = 0.f;

    // ---- stage 1 ----
    mma_stage(sm, W1, tid, lane, m0, n0, acc);

    // ---- epilogue 1: bias+relu, write H1 over A (all stage-1 reads done) ----
    __syncthreads();
#pragma unroll
    for (int mt = 0; mt < 2; mt++) {
#pragma unroll
        for (int nt = 0; nt < 4; nt++) {
            int col = n0 + nt * 8 + 2 * tig;
            float bia0 = bs1[col], bia1 = bs1[col + 1];
            int kp2 = (n0 >> 1) + nt * 4 + tig;
            int ra = m0 + mt * 16 + gid;
            float v0 = fmaxf(acc[mt][nt][0] + bia0, 0.f);
            float v1 = fmaxf(acc[mt][nt][1] + bia1, 0.f);
            float v2 = fmaxf(acc[mt][nt][2] + bia0, 0.f);
            float v3 = fmaxf(acc[mt][nt][3] + bia1, 0.f);
            __nv_bfloat16 h0, l0, h1, l1, h2, l2, h3, l3;
            split_bf16(v0, h0, l0); split_bf16(v1, h1, l1);
            split_bf16(v2, h2, l2); split_bf16(v3, h3, l3);
            int aA = a_addr(ra, kp2);
            int aB = a_addr(ra + 8, kp2);
            sm[A_HI + aA] = pack2(h0, h1);
            sm[A_LO + aA] = pack2(l0, l1);
            sm[A_HI + aB] = pack2(h2, h3);
            sm[A_LO + aB] = pack2(l2, l3);
#pragma unroll
            for (int q = 0; q < 4; q++) acc[mt][nt][q] = 0.f;
        }
    }
    // stage 2's first __syncthreads orders these writes before A-frag reads

    // ---- stage 2 ----
    mma_stage(sm, W2, tid, lane, m0, n0, acc);

    // ---- epilogue 2: bias (+relu), float2 STG ----
#pragma unroll
    for (int mt = 0; mt < 2; mt++) {
#pragma unroll
        for (int nt = 0; nt < 4; nt++) {
            int col = n0 + nt * 8 + 2 * tig;
            float bia0 = bs2[col], bia1 = bs2[col + 1];
            int node0 = row0 + m0 + mt * 16 + gid;
            float2 o0, o1;
            o0.x = acc[mt][nt][0] + bia0; o0.y = acc[mt][nt][1] + bia1;
            o1.x = acc[mt][nt][2] + bia0; o1.y = acc[mt][nt][3] + bia1;
            if (reluOut) {
                o0.x = fmaxf(o0.x, 0.f); o0.y = fmaxf(o0.y, 0.f);
                o1.x = fmaxf(o1.x, 0.f); o1.y = fmaxf(o1.y, 0.f);
            }
            if (node0 < N_NODES)
                *(float2*)(O + (size_t)node0 * HID + col) = o0;
            if (node0 + 8 < N_NODES)
                *(float2*)(O + (size_t)(node0 + 8) * HID + col) = o1;
        }
    }
}

// ---------------- pooling boundaries (batch is sorted int32) ---------------
__global__ void boundaries_kernel(const int* __restrict__ batch) {
    int i = blockIdx.x * blockDim.x + threadIdx.x;
    if (i >= N_NODES) return;
    int b = batch[i];
    if (i == 0) {
        for (int g = 0; g <= b; g++) g_start[g] = 0;
    } else {
        int p = batch[i - 1];
        if (p < b)
            for (int g = p + 1; g <= b; g++) g_start[g] = i;
    }
    if (i == N_NODES - 1) {
        for (int g = b + 1; g <= NUM_GRAPHS; g++) g_start[g] = N_NODES;
    }
}

// ---------------- fused global_add_pool + final linear ---------------------
__global__ void pool_final_kernel(const float* __restrict__ lw,
                                  const float* __restrict__ lb,
                                  float* __restrict__ out,
                                  int in_sel) {
    const float* __restrict__ h = (in_sel == 0) ? g_h0 : g_h1;
    int g = blockIdx.x;
    int c = threadIdx.x;   // 128 threads
    int s = g_start[g], e = g_start[g + 1];
    float acc = 0.f;
    for (int n = s; n < e; n++) acc += h[(size_t)n * HID + c];
    __shared__ float sp[HID];
    sp[c] = acc;
    __syncthreads();
    if (c < OUT_CH) {
        float o = lb[c];
#pragma unroll 8
        for (int k = 0; k < HID; k++) o += sp[k] * lw[k * OUT_CH + c];
        out[g * OUT_CH + c] = o;
    }
}

// ---------------- host: kernel launches ONLY -------------------------------
extern "C" void kernel_launch(void* const* d_in, const int* in_sizes, int n_in,
                              void* d_out, int out_size) {
    const float* x     = (const float*)d_in[0];
    const int*   ei    = (const int*)d_in[1];     // int32 (JAX x64 disabled)
    const int*   batch = (const int*)d_in[2];     // int32
    const float* w1[3] = {(const float*)d_in[3],  (const float*)d_in[7],  (const float*)d_in[11]};
    const float* b1[3] = {(const float*)d_in[4],  (const float*)d_in[8],  (const float*)d_in[12]};
    const float* w2[3] = {(const float*)d_in[5],  (const float*)d_in[9],  (const float*)d_in[13]};
    const float* b2[3] = {(const float*)d_in[6],  (const float*)d_in[10], (const float*)d_in[14]};
    const float* lin_w = (const float*)d_in[15];
    const float* lin_b = (const float*)d_in[16];
    float* out = (float*)d_out;

    // ---- CSR build (deterministic per launch) ----
    zero_cnt_kernel<<<(N_NODES + 255) / 256, 256>>>();
    hist_kernel<<<(N_EDGES + 255) / 256, 256>>>(ei);
    scan_local_kernel<<<(N_NODES + 1023) / 1024, 1024>>>();
    scan_sums_kernel<<<1, 32>>>((N_NODES + 1023) / 1024);
    scan_add_kernel<<<(N_NODES + 255) / 256, 256>>>();
    zero_cnt_kernel<<<(N_NODES + 255) / 256, 256>>>();
    fill_kernel<<<(N_EDGES + 255) / 256, 256>>>(ei);
    boundaries_kernel<<<(N_NODES + 255) / 256, 256>>>(batch);

    // ---- 3 GIN layers (split: aggregate then MLP) ----
    const int agg_blocks = (N_NODES * 32 + 255) / 256;
    const int mlp_blocks = (N_NODES + 63) / 64;

    aggregate_kernel<<<agg_blocks, 256>>>(x, -1);
    mlp_mma_kernel<<<mlp_blocks, 256>>>(w1[0], b1[0], w2[0], b2[0], 0, 1);
    aggregate_kernel<<<agg_blocks, 256>>>(nullptr, 0);
    mlp_mma_kernel<<<mlp_blocks, 256>>>(w1[1], b1[1], w2[1], b2[1], 1, 1);
    aggregate_kernel<<<agg_blocks, 256>>>(nullptr, 1);
    mlp_mma_kernel<<<mlp_blocks, 256>>>(w1[2], b1[2], w2[2], b2[2], 0, 0);

    // ---- pool + final linear ----
    pool_final_kernel<<<NUM_GRAPHS, 128>>>(lin_w, lin_b, out, 0);
}

// round 9
// speedup vs baseline: 1.2416x; 1.0619x over previous
#include <cuda_runtime.h>
#include <cuda_bf16.h>
#include <stdint.h>

#define N_NODES    100000
#define N_EDGES    1600000
#define HID        128
#define OUT_CH     10
#define NUM_GRAPHS 512

// ---------------- scratch (static device globals; kernel launches are the
// ONLY host API used in kernel_launch) ---------------------------------------
__device__ float g_h0[N_NODES * HID];
__device__ float g_h1[N_NODES * HID];
__device__ float g_z [N_NODES * HID];
__device__ int   g_rowptr[N_NODES + 1];
__device__ int   g_cnt[N_NODES];
__device__ int   g_local[N_NODES];
__device__ int   g_bsums[128];
__device__ int   g_col[N_EDGES];
__device__ int   g_start[NUM_GRAPHS + 1];

__device__ __forceinline__ const float* sel_buf(int sel, const float* ext) {
    if (sel == 0) return g_h0;
    if (sel == 1) return g_h1;
    return ext;
}

__device__ __forceinline__ void split_bf16(float x, __nv_bfloat16& h, __nv_bfloat16& l) {
    h = __float2bfloat16(x);
    l = __float2bfloat16(x - __bfloat162float(h));
}
__device__ __forceinline__ uint32_t pack2(__nv_bfloat16 lo, __nv_bfloat16 hi) {
    return (uint32_t)__bfloat16_as_ushort(lo) | ((uint32_t)__bfloat16_as_ushort(hi) << 16);
}
__device__ __forceinline__ void mma_bf16(float c[4], uint32_t a0, uint32_t a1,
                                         uint32_t a2, uint32_t a3,
                                         uint32_t b0, uint32_t b1) {
    asm volatile(
        "mma.sync.aligned.m16n8k16.row.col.f32.bf16.bf16.f32 "
        "{%0,%1,%2,%3}, {%4,%5,%6,%7}, {%8,%9}, {%0,%1,%2,%3};\n"
        : "+f"(c[0]), "+f"(c[1]), "+f"(c[2]), "+f"(c[3])
        : "r"(a0), "r"(a1), "r"(a2), "r"(a3), "r"(b0), "r"(b1));
}

// ---------------- zero counters --------------------------------------------
__global__ void zero_cnt_kernel() {
    int i = blockIdx.x * blockDim.x + threadIdx.x;
    if (i < N_NODES) g_cnt[i] = 0;
}

// ---------------- CSR build (edge_index is int32) ---------------------------
__global__ void hist_kernel(const int* __restrict__ ei) {
    int e = blockIdx.x * blockDim.x + threadIdx.x;
    if (e >= N_EDGES) return;
    atomicAdd(&g_cnt[ei[N_EDGES + e]], 1);
}

__global__ void scan_local_kernel() {
    __shared__ int s[1024];
    int tid = threadIdx.x;
    int i = blockIdx.x * 1024 + tid;
    int v = (i < N_NODES) ? g_cnt[i] : 0;
    s[tid] = v;
    __syncthreads();
    for (int off = 1; off < 1024; off <<= 1) {
        int t = (tid >= off) ? s[tid - off] : 0;
        __syncthreads();
        s[tid] += t;
        __syncthreads();
    }
    if (i < N_NODES) g_local[i] = s[tid] - v;
    if (tid == 1023) g_bsums[blockIdx.x] = s[1023];
}

// parallel exclusive scan over block sums (was 6.3us serial)
__global__ void scan_sums_kernel(int nb) {
    __shared__ int s[128];
    int t = threadIdx.x;
    int v = (t < nb) ? g_bsums[t] : 0;
    s[t] = v;
    __syncthreads();
    for (int off = 1; off < 128; off <<= 1) {
        int tmp = (t >= off) ? s[t - off] : 0;
        __syncthreads();
        s[t] += tmp;
        __syncthreads();
    }
    if (t < nb) g_bsums[t] = s[t] - v;   // exclusive
}

// also re-zeroes g_cnt (fill uses it as a cursor) — saves a launch
__global__ void scan_add_kernel() {
    int i = blockIdx.x * blockDim.x + threadIdx.x;
    if (i < N_NODES) {
        g_rowptr[i] = g_local[i] + g_bsums[i >> 10];
        g_cnt[i] = 0;
    }
    if (i == 0) g_rowptr[N_NODES] = N_EDGES;
}

__global__ void fill_kernel(const int* __restrict__ ei) {
    int e = blockIdx.x * blockDim.x + threadIdx.x;
    if (e >= N_EDGES) return;
    int d = ei[N_EDGES + e];
    int s = ei[e];
    int pos = g_rowptr[d] + atomicAdd(&g_cnt[d], 1);
    g_col[pos] = s;
}

// ---------------- aggregation: g_z = h + sum_{j in N(i)} h[j] --------------
__global__ __launch_bounds__(256) void aggregate_kernel(const float* __restrict__ x_ext,
                                                        int in_sel) {
    const float* __restrict__ h = sel_buf(in_sel, x_ext);
    int node = (blockIdx.x * blockDim.x + threadIdx.x) >> 5;
    int lane = threadIdx.x & 31;
    if (node >= N_NODES) return;
    int beg = g_rowptr[node];
    int end = g_rowptr[node + 1];
    int co = lane * 4;
    float4 acc = *(const float4*)(h + (size_t)node * HID + co);
    int e = beg;
    for (; e + 4 <= end; e += 4) {
        int s0 = g_col[e], s1 = g_col[e + 1], s2 = g_col[e + 2], s3 = g_col[e + 3];
        float4 v0 = *(const float4*)(h + (size_t)s0 * HID + co);
        float4 v1 = *(const float4*)(h + (size_t)s1 * HID + co);
        float4 v2 = *(const float4*)(h + (size_t)s2 * HID + co);
        float4 v3 = *(const float4*)(h + (size_t)s3 * HID + co);
        acc.x += v0.x + v1.x + v2.x + v3.x;
        acc.y += v0.y + v1.y + v2.y + v3.y;
        acc.z += v0.z + v1.z + v2.z + v3.z;
        acc.w += v0.w + v1.w + v2.w + v3.w;
    }
    for (; e < end; e++) {
        int s = g_col[e];
        float4 v = *(const float4*)(h + (size_t)s * HID + co);
        acc.x += v.x; acc.y += v.y; acc.z += v.z; acc.w += v.w;
    }
    *(float4*)(g_z + (size_t)node * HID + co) = acc;
}

// ============ HMMA MLP: bf16 hi/lo 3-term, fragment-major, pipelined W ======
// Block: 64 nodes x 128 out-ch, 256 threads = 8 warps (2m x 4n), warp 32x32.
// A layout: per (16-row mtile, 8-kpair kgroup) 132-word tile; word (r,kp) at
//   lane'=(r&7)*4+(kp&3), w=((r>>3)&1)+2*((kp>>2)&1)  -> frag = 1 LDS.128.
// B panel layout: per 8-col ntile 66-word tile; word (n,kp) at
//   lane'=(n&7)*4+(kp&3), w=(kp>>2)&1                 -> frag = 1 LDS.64.
// W panels are software-pipelined: LDG of panel p+1 overlaps panel p's MMAs.
#define A_HI  0
#define A_LO  4224
#define WB_HI 8448
#define WB_LO 9504
#define BS1   10560
#define BS2   10688
#define SM_WORDS 10816

__device__ __forceinline__ int a_addr(int r, int kp) {
    return (((r >> 4) * 8) + (kp >> 3)) * 132
         + ((r & 7) * 4 + (kp & 3)) * 4
         + ((r >> 3) & 1) + 2 * ((kp >> 2) & 1);
}
__device__ __forceinline__ int b_addr(int n, int kp) {
    return (n >> 3) * 66 + ((n & 7) * 4 + (kp & 3)) * 2 + ((kp >> 2) & 1);
}

__device__ __forceinline__ void mma_stage(uint32_t* sm, const float* __restrict__ W,
                                          int tid, int lane, int m0, int n0,
                                          float acc[2][4][4]) {
    int m016 = m0 >> 4;        // 0 or 2
    int n08  = n0 >> 3;        // 0 or 4

    // preload panel 0 into regs
    float w0[4], w1[4];
#pragma unroll
    for (int it = 0; it < 4; it++) {
        int i = it * 256 + tid;
        int n = i & 127, kpl = i >> 7;
        w0[it] = W[(kpl * 2) * HID + n];
        w1[it] = W[(kpl * 2 + 1) * HID + n];
    }

#pragma unroll 1
    for (int p = 0; p < 8; p++) {
        __syncthreads();   // previous panel consumed (also orders A writes, p=0)
#pragma unroll
        for (int it = 0; it < 4; it++) {
            int i = it * 256 + tid;
            int n = i & 127, kpl = i >> 7;
            __nv_bfloat16 h0, l0, h1, l1;
            split_bf16(w0[it], h0, l0);
            split_bf16(w1[it], h1, l1);
            int ba = b_addr(n, kpl);
            sm[WB_HI + ba] = pack2(h0, h1);
            sm[WB_LO + ba] = pack2(l0, l1);
        }
        __syncthreads();   // panel visible

        // issue next panel's LDG now — latency hides behind the MMAs below
        if (p < 7) {
#pragma unroll
            for (int it = 0; it < 4; it++) {
                int i = it * 256 + tid;
                int n = i & 127, kpl = i >> 7;
                int kg = (p + 1) * 16 + kpl * 2;
                w0[it] = W[kg * HID + n];
                w1[it] = W[(kg + 1) * HID + n];
            }
        }

        // A fragments: one LDS.128 per (mtile, hi/lo)
        uint4 ah[2], al[2];
#pragma unroll
        for (int mt = 0; mt < 2; mt++) {
            int base = ((m016 + mt) * 8 + p) * 132 + lane * 4;
            ah[mt] = *(const uint4*)&sm[A_HI + base];
            al[mt] = *(const uint4*)&sm[A_LO + base];
        }
#pragma unroll
        for (int nt = 0; nt < 4; nt++) {
            int nb = (n08 + nt) * 66 + lane * 2;
            uint2 bh = *(const uint2*)&sm[WB_HI + nb];
            uint2 bl = *(const uint2*)&sm[WB_LO + nb];
#pragma unroll
            for (int mt = 0; mt < 2; mt++) {
                mma_bf16(acc[mt][nt], ah[mt].x, ah[mt].y, ah[mt].z, ah[mt].w, bh.x, bh.y);
                mma_bf16(acc[mt][nt], ah[mt].x, ah[mt].y, ah[mt].z, ah[mt].w, bl.x, bl.y);
                mma_bf16(acc[mt][nt], al[mt].x, al[mt].y, al[mt].z, al[mt].w, bh.x, bh.y);
            }
        }
    }
}

__global__ __launch_bounds__(256, 2) void mlp_mma_kernel(const float* __restrict__ W1,
                                                         const float* __restrict__ B1,
                                                         const float* __restrict__ W2,
                                                         const float* __restrict__ B2,
                                                         int out_sel, int reluOut) {
    __shared__ __align__(16) uint32_t sm[SM_WORDS];
    float* O = (out_sel == 0) ? g_h0 : g_h1;
    float* bs1 = (float*)(sm + BS1);
    float* bs2 = (float*)(sm + BS2);

    int tid  = threadIdx.x;
    int lane = tid & 31, warp = tid >> 5;
    int gid  = lane >> 2, tig = lane & 3;
    int m0   = (warp & 1) * 32;
    int n0   = (warp >> 1) * 32;
    int row0 = blockIdx.x * 64;

    if (tid < 128) { bs1[tid] = B1[tid]; bs2[tid] = B2[tid]; }

    // ---- load Z tile, hi/lo split, fragment-major A layout ----
#pragma unroll
    for (int p = 0; p < 8; p++) {
        int idx = p * 256 + tid;          // 0..2047
        int r  = idx >> 5;                // node row 0..63
        int c4 = (idx & 31) << 2;         // channel 0..124
        float4 v = make_float4(0.f, 0.f, 0.f, 0.f);
        if (row0 + r < N_NODES)
            v = *(const float4*)(g_z + (size_t)(row0 + r) * HID + c4);
        int kp = c4 >> 1;
        __nv_bfloat16 hx, lx, hy, ly, hz, lz, hw, lw;
        split_bf16(v.x, hx, lx); split_bf16(v.y, hy, ly);
        split_bf16(v.z, hz, lz); split_bf16(v.w, hw, lw);
        int a0i = a_addr(r, kp);
        int a1i = a_addr(r, kp + 1);
        sm[A_HI + a0i] = pack2(hx, hy);
        sm[A_HI + a1i] = pack2(hz, hw);
        sm[A_LO + a0i] = pack2(lx, ly);
        sm[A_LO + a1i] = pack2(lz, lw);
    }
    // ordering: A writes precede A-frag reads via mma_stage's barriers

    float acc[2][4][4];
#pragma unroll
    for (int mt = 0; mt < 2; mt++)
#pragma unroll
        for (int nt = 0; nt < 4; nt++)
#pragma unroll
            for (int q = 0; q < 4; q++) acc[mt][nt][q] = 0.f;

    // ---- stage 1 ----
    mma_stage(sm, W1, tid, lane, m0, n0, acc);

    // ---- epilogue 1: bias+relu, write H1 over A (all stage-1 reads done) ----
    __syncthreads();
#pragma unroll
    for (int mt = 0; mt < 2; mt++) {
#pragma unroll
        for (int nt = 0; nt < 4; nt++) {
            int col = n0 + nt * 8 + 2 * tig;
            float bia0 = bs1[col], bia1 = bs1[col + 1];
            int kp2 = (n0 >> 1) + nt * 4 + tig;
            int ra = m0 + mt * 16 + gid;
            float v0 = fmaxf(acc[mt][nt][0] + bia0, 0.f);
            float v1 = fmaxf(acc[mt][nt][1] + bia1, 0.f);
            float v2 = fmaxf(acc[mt][nt][2] + bia0, 0.f);
            float v3 = fmaxf(acc[mt][nt][3] + bia1, 0.f);
            __nv_bfloat16 h0, l0, h1, l1, h2, l2, h3, l3;
            split_bf16(v0, h0, l0); split_bf16(v1, h1, l1);
            split_bf16(v2, h2, l2); split_bf16(v3, h3, l3);
            int aA = a_addr(ra, kp2);
            int aB = a_addr(ra + 8, kp2);
            sm[A_HI + aA] = pack2(h0, h1);
            sm[A_LO + aA] = pack2(l0, l1);
            sm[A_HI + aB] = pack2(h2, h3);
            sm[A_LO + aB] = pack2(l2, l3);
#pragma unroll
            for (int q = 0; q < 4; q++) acc[mt][nt][q] = 0.f;
        }
    }
    // stage 2's first __syncthreads orders these writes before A-frag reads

    // ---- stage 2 ----
    mma_stage(sm, W2, tid, lane, m0, n0, acc);

    // ---- epilogue 2: bias (+relu), float2 STG ----
#pragma unroll
    for (int mt = 0; mt < 2; mt++) {
#pragma unroll
        for (int nt = 0; nt < 4; nt++) {
            int col = n0 + nt * 8 + 2 * tig;
            float bia0 = bs2[col], bia1 = bs2[col + 1];
            int node0 = row0 + m0 + mt * 16 + gid;
            float2 o0, o1;
            o0.x = acc[mt][nt][0] + bia0; o0.y = acc[mt][nt][1] + bia1;
            o1.x = acc[mt][nt][2] + bia0; o1.y = acc[mt][nt][3] + bia1;
            if (reluOut) {
                o0.x = fmaxf(o0.x, 0.f); o0.y = fmaxf(o0.y, 0.f);
                o1.x = fmaxf(o1.x, 0.f); o1.y = fmaxf(o1.y, 0.f);
            }
            if (node0 < N_NODES)
                *(float2*)(O + (size_t)node0 * HID + col) = o0;
            if (node0 + 8 < N_NODES)
                *(float2*)(O + (size_t)(node0 + 8) * HID + col) = o1;
        }
    }
}

// ---------------- pooling boundaries (batch is sorted int32) ---------------
__global__ void boundaries_kernel(const int* __restrict__ batch) {
    int i = blockIdx.x * blockDim.x + threadIdx.x;
    if (i >= N_NODES) return;
    int b = batch[i];
    if (i == 0) {
        for (int g = 0; g <= b; g++) g_start[g] = 0;
    } else {
        int p = batch[i - 1];
        if (p < b)
            for (int g = p + 1; g <= b; g++) g_start[g] = i;
    }
    if (i == N_NODES - 1) {
        for (int g = b + 1; g <= NUM_GRAPHS; g++) g_start[g] = N_NODES;
    }
}

// ---------------- fused global_add_pool + final linear ---------------------
__global__ void pool_final_kernel(const float* __restrict__ lw,
                                  const float* __restrict__ lb,
                                  float* __restrict__ out,
                                  int in_sel) {
    const float* __restrict__ h = (in_sel == 0) ? g_h0 : g_h1;
    int g = blockIdx.x;
    int c = threadIdx.x;   // 128 threads
    int s = g_start[g], e = g_start[g + 1];
    float acc = 0.f;
    for (int n = s; n < e; n++) acc += h[(size_t)n * HID + c];
    __shared__ float sp[HID];
    sp[c] = acc;
    __syncthreads();
    if (c < OUT_CH) {
        float o = lb[c];
#pragma unroll 8
        for (int k = 0; k < HID; k++) o += sp[k] * lw[k * OUT_CH + c];
        out[g * OUT_CH + c] = o;
    }
}

// ---------------- host: kernel launches ONLY -------------------------------
extern "C" void kernel_launch(void* const* d_in, const int* in_sizes, int n_in,
                              void* d_out, int out_size) {
    const float* x     = (const float*)d_in[0];
    const int*   ei    = (const int*)d_in[1];     // int32 (JAX x64 disabled)
    const int*   batch = (const int*)d_in[2];     // int32
    const float* w1[3] = {(const float*)d_in[3],  (const float*)d_in[7],  (const float*)d_in[11]};
    const float* b1[3] = {(const float*)d_in[4],  (const float*)d_in[8],  (const float*)d_in[12]};
    const float* w2[3] = {(const float*)d_in[5],  (const float*)d_in[9],  (const float*)d_in[13]};
    const float* b2[3] = {(const float*)d_in[6],  (const float*)d_in[10], (const float*)d_in[14]};
    const float* lin_w = (const float*)d_in[15];
    const float* lin_b = (const float*)d_in[16];
    float* out = (float*)d_out;

    // ---- CSR build (deterministic per launch) ----
    zero_cnt_kernel<<<(N_NODES + 255) / 256, 256>>>();
    hist_kernel<<<(N_EDGES + 255) / 256, 256>>>(ei);
    scan_local_kernel<<<(N_NODES + 1023) / 1024, 1024>>>();
    scan_sums_kernel<<<1, 128>>>((N_NODES + 1023) / 1024);
    scan_add_kernel<<<(N_NODES + 255) / 256, 256>>>();   // also zeroes g_cnt
    fill_kernel<<<(N_EDGES + 255) / 256, 256>>>(ei);
    boundaries_kernel<<<(N_NODES + 255) / 256, 256>>>(batch);

    // ---- 3 GIN layers (split: aggregate then MLP) ----
    const int agg_blocks = (N_NODES * 32 + 255) / 256;
    const int mlp_blocks = (N_NODES + 63) / 64;

    aggregate_kernel<<<agg_blocks, 256>>>(x, -1);
    mlp_mma_kernel<<<mlp_blocks, 256>>>(w1[0], b1[0], w2[0], b2[0], 0, 1);
    aggregate_kernel<<<agg_blocks, 256>>>(nullptr, 0);
    mlp_mma_kernel<<<mlp_blocks, 256>>>(w1[1], b1[1], w2[1], b2[1], 1, 1);
    aggregate_kernel<<<agg_blocks, 256>>>(nullptr, 1);
    mlp_mma_kernel<<<mlp_blocks, 256>>>(w1[2], b1[2], w2[2], b2[2], 0, 0);

    // ---- pool + final linear ----
    pool_final_kernel<<<NUM_GRAPHS, 128>>>(lin_w, lin_b, out, 0);
}